// round 16
// baseline (speedup 1.0000x reference)
#include <cuda_runtime.h>
#include <math.h>

#define NB 8
#define NT 4096
#define ND 512
#define NSER (NB * ND)   // 4096 series
#define NPAIR (NSER / 2) // 2048 packed pair-series
#define TOPK 7
#define TCHUNK 64

// Scratch: stage-1 FFT output per pair-series, and per-series coefficients
__device__ float2 g_y[(size_t)NPAIR * NT];        // 64 MB
__device__ float4 g_coef[NSER * TOPK];

// ---------------------------------------------------------------------------
// Complex helpers + 16-point DFT (shared by both kernels)
// ---------------------------------------------------------------------------
__device__ __forceinline__ float2 cmul(float2 a, float2 b) {
    return make_float2(a.x * b.x - a.y * b.y, a.x * b.y + a.y * b.x);
}

__device__ __forceinline__ void dft4(float2& A, float2& B, float2& C, float2& D) {
    float2 apc  = make_float2(A.x + C.x, A.y + C.y);
    float2 amc  = make_float2(A.x - C.x, A.y - C.y);
    float2 bpd  = make_float2(B.x + D.x, B.y + D.y);
    float2 jbmd = make_float2(-(B.y - D.y), B.x - D.x);   // i*(B-D)
    A = make_float2(apc.x + bpd.x, apc.y + bpd.y);
    B = make_float2(amc.x - jbmd.x, amc.y - jbmd.y);
    C = make_float2(apc.x - bpd.x, apc.y - bpd.y);
    D = make_float2(amc.x + jbmd.x, amc.y + jbmd.y);
}

#define C8f  0.70710678118654752f
#define C16f 0.92387953251128676f
#define S16f 0.38268343236508977f

// In-place 16-point DFT. After this, slot (4*u1 + u2) holds X[u1 + 4*u2].
__device__ __forceinline__ void dft16(float2* a) {
#pragma unroll
    for (int r2 = 0; r2 < 4; r2++)
        dft4(a[r2], a[r2 + 4], a[r2 + 8], a[r2 + 12]);
    a[5]  = cmul(a[5],  make_float2( C16f, -S16f));
    a[6]  = cmul(a[6],  make_float2( C8f,  -C8f ));
    a[7]  = cmul(a[7],  make_float2( S16f, -C16f));
    a[9]  = cmul(a[9],  make_float2( C8f,  -C8f ));
    a[10] = make_float2(a[10].y, -a[10].x);
    a[11] = cmul(a[11], make_float2(-C8f,  -C8f ));
    a[13] = cmul(a[13], make_float2( S16f, -C16f));
    a[14] = cmul(a[14], make_float2(-C8f,  -C8f ));
    a[15] = cmul(a[15], make_float2(-C16f,  S16f));
#pragma unroll
    for (int u1 = 0; u1 < 4; u1++)
        dft4(a[4 * u1 + 0], a[4 * u1 + 1], a[4 * u1 + 2], a[4 * u1 + 3]);
}

// Apply a[slot(u)] *= w1^u for u=1..15, 4 independent chains (depth <= 4)
__device__ __forceinline__ void twiddle16(float2* a, float2 w1) {
    float2 w2 = cmul(w1, w1);
    float2 w3 = cmul(w2, w1);
    float2 w4 = cmul(w2, w2);
    float2 c1 = w1, c2 = w2, c3 = w3, c0 = w4;
#pragma unroll
    for (int g = 0; g < 4; g++) {
        int u1 = 4 * g + 1, u2 = 4 * g + 2, u3 = 4 * g + 3, u4 = 4 * g + 4;
        a[((u1 & 3) << 2) | (u1 >> 2)] = cmul(a[((u1 & 3) << 2) | (u1 >> 2)], c1);
        a[((u2 & 3) << 2) | (u2 >> 2)] = cmul(a[((u2 & 3) << 2) | (u2 >> 2)], c2);
        a[((u3 & 3) << 2) | (u3 >> 2)] = cmul(a[((u3 & 3) << 2) | (u3 >> 2)], c3);
        if (u4 < 16)
            a[((u4 & 3) << 2) | (u4 >> 2)] = cmul(a[((u4 & 3) << 2) | (u4 >> 2)], c0);
        if (g < 3) {
            c1 = cmul(c1, w4);
            c2 = cmul(c2, w4);
            c3 = cmul(c3, w4);
            c0 = cmul(c0, w4);
        }
    }
}

// ---------------------------------------------------------------------------
// Kernel 1: fused transpose + FFT stage 1.
// Block: (i0 = 16*bx, pairs e0 = 16*by, batch b). Loads rows t = i0+iloc+256*r
// (each row coalesced 32 d's), packs z = x[t,2e] + i*x[t,2e+1], computes
// g_y[pair][16*i + u] = W4096^{i*u} * sum_r z[i+256r] * W16^{ur}.
// ---------------------------------------------------------------------------
#define TILEW 36   // 32 + 4 floats pad (keeps float4 alignment: 36*4=144 B)

__global__ __launch_bounds__(256) void fft16a_kernel(const float* __restrict__ in) {
    __shared__ float smem[256 * TILEW];     // 36864 B; reused as yout[16][257] f2
    float*  tile = smem;
    float2* yout = (float2*)smem;           // [16 pairs][257] (32896 B < 36864)

    int tid = threadIdx.x;
    int b  = blockIdx.z;
    int i0 = blockIdx.x * 16;
    int e0 = blockIdx.y * 16;
    int d0 = e0 * 2;

    // Load 256 rows (m = iloc*16 + r -> t = i0 + iloc + 256*r), 32 d's each
#pragma unroll
    for (int j = 0; j < 8; j++) {
        int lidx = tid + 256 * j;       // float4 id in [0, 2048)
        int m  = lidx >> 3;
        int c4 = lidx & 7;
        int iloc = m >> 4, r = m & 15;
        int t = i0 + iloc + 256 * r;
        float4 v = *(const float4*)(in + ((size_t)b * NT + t) * ND + d0 + 4 * c4);
        *(float4*)&tile[m * TILEW + 4 * c4] = v;
    }
    __syncthreads();

    // Each thread: pair e, sub-index iloc -> global i = i0 + iloc
    int e = tid & 15, iloc = tid >> 4;
    int i = i0 + iloc;
    float2 a[16];
#pragma unroll
    for (int r = 0; r < 16; r++) {
        int m = iloc * 16 + r;
        a[r] = make_float2(tile[m * TILEW + 2 * e], tile[m * TILEW + 2 * e + 1]);
    }
    __syncthreads();   // all reads done before yout overwrites tile

    dft16(a);
    {
        float sw, cw;
        sincospif((float)i * (1.0f / 2048.0f), &sw, &cw);
        twiddle16(a, make_float2(cw, -sw));   // w1 = W4096^i
    }
#pragma unroll
    for (int u = 0; u < 16; u++) {
        int s = ((u & 3) << 2) | (u >> 2);    // slot holding X[u]
        yout[e * 257 + 16 * iloc + u] = a[s];
    }
    __syncthreads();

    // Coalesced write: per pair 256 contiguous complex at offset 16*i0
#pragma unroll
    for (int j = 0; j < 8; j++) {
        int widx = tid + 256 * j;       // float4 id in [0, 2048)
        int pair = widx >> 7;
        int c    = widx & 127;
        float2 lo = yout[pair * 257 + 2 * c];
        float2 hi = yout[pair * 257 + 2 * c + 1];
        float2* dst = g_y + (size_t)(b * 256 + e0 + pair) * NT + 16 * i0 + 2 * c;
        *(float4*)dst = make_float4(lo.x, lo.y, hi.x, hi.y);
    }
}

// ---------------------------------------------------------------------------
// Kernel 2: FFT stages 2+3 (radix-16 Stockham) + top-7 per series
// ---------------------------------------------------------------------------
template<int S, int SH, bool TW>
__device__ __forceinline__ void fft_stage(float2* buf, int i) {
    float2 a[16];
#pragma unroll
    for (int r = 0; r < 16; r++) {
        int idx = i + 256 * r;
        a[r] = buf[idx + (idx >> 4)];
    }
    __syncthreads();
    dft16(a);
    int q = i & (S - 1);
    int p = i >> SH;
    if (TW) {
        float sw, cw;
        sincospif((float)(S * p) * (1.0f / 2048.0f), &sw, &cw);
        twiddle16(a, make_float2(cw, -sw));
    }
    int ob = q + ((p * S) << 4);
#pragma unroll
    for (int u = 0; u < 16; u++) {
        int s = ((u & 3) << 2) | (u >> 2);
        int idx = ob + S * u;
        buf[idx + (idx >> 4)] = a[s];
    }
    __syncthreads();
}

__device__ __forceinline__ void grp_bar(int id) {
    asm volatile("bar.sync %0, %1;" :: "r"(id), "r"(128) : "memory");
}

// Top-7 over one half-series, executed by a 128-thread warp group.
__device__ __forceinline__ void topk_group(float* amp, const float2* buf,
                                           unsigned long long* wm,
                                           int gtid, int gwid, int lane,
                                           int series, bool halfB, int barid) {
    unsigned long long myBest = 0ull;
#pragma unroll
    for (int r = 0; r < 16; r++) {
        int k = gtid + 128 * r;
        unsigned long long pk =
            ((unsigned long long)__float_as_uint(amp[k]) << 32) | (unsigned)(4095 - k);
        if (pk > myBest) myBest = pk;
    }
    for (int it = 0; it < TOPK; it++) {
        unsigned long long best = myBest;
#pragma unroll
        for (int off = 16; off; off >>= 1) {
            unsigned long long o = __shfl_xor_sync(0xffffffffu, best, off);
            if (o > best) best = o;
        }
        unsigned long long* ws = wm + (it & 1) * 4;
        if (lane == 0) ws[gwid] = best;
        grp_bar(barid);
        unsigned long long bb = ws[0];
#pragma unroll
        for (int w = 1; w < 4; w++) if (ws[w] > bb) bb = ws[w];
        int kstar = 4095 - (int)(unsigned)(bb & 0xffffffffull);
        if (gtid == (kstar & 127)) {
            amp[kstar] = 0.0f;    // remove winner (only this thread reads it)
            float2 zk = buf[kstar + (kstar >> 4)];
            int n = NT - kstar;
            float2 zn = buf[n + (n >> 4)];
            float re2, im2;   // 2*Re(X), 2*Im(X)
            if (!halfB) { re2 = zk.x + zn.x; im2 = zk.y - zn.y; }
            else        { re2 = zk.y + zn.y; im2 = zn.x - zk.x; }
            g_coef[series * TOPK + it] = make_float4((float)kstar, re2, im2, 0.0f);
            myBest = 0ull;
#pragma unroll
            for (int r = 0; r < 16; r++) {
                int k = gtid + 128 * r;
                unsigned long long pk =
                    ((unsigned long long)__float_as_uint(amp[k]) << 32) | (unsigned)(4095 - k);
                if (pk > myBest) myBest = pk;
            }
        }
    }
}

extern __shared__ float2 sdyn[];

__global__ __launch_bounds__(256) void fft_topk_kernel() {
    float2* buf  = sdyn;                     // 4352 float2 (padded 4096)
    float*  ampA = (float*)(sdyn + 4352);    // 2048 floats
    float*  ampB = ampA + 2048;              // 2048 floats
    __shared__ unsigned long long wmax[16];

    int tid = threadIdx.x;
    int pairIdx = blockIdx.x;                // b*256 + e
    int b = pairIdx >> 8;
    int e = pairIdx & 255;
    int series0 = b * ND + 2 * e;

    // Load stage-1 output: coalesced float4 (2 complex per load)
    const float4* gy4 = (const float4*)(g_y + (size_t)pairIdx * NT);
#pragma unroll
    for (int j = 0; j < 8; j++) {
        float4 v = gy4[tid + 256 * j];
        int i0 = 2 * (tid + 256 * j);
        buf[(i0 + 0) + ((i0 + 0) >> 4)] = make_float2(v.x, v.y);
        buf[(i0 + 1) + ((i0 + 1) >> 4)] = make_float2(v.z, v.w);
    }
    __syncthreads();

    fft_stage<16,  4, true >(buf, tid);
    fft_stage<256, 8, false>(buf, tid);

    // Unpack amplitudes (x4, ranking-invariant) for k in [0, 2048)
    // X_a[k] = (Z[k]+conj(Z[N-k]))/2, X_b[k] = -i(Z[k]-conj(Z[N-k]))/2
#pragma unroll
    for (int r = 0; r < 8; r++) {
        int k = tid + 256 * r;
        if (k == 0) {
            ampA[0] = 0.0f; ampB[0] = 0.0f;   // exclude DC
        } else {
            float2 zk = buf[k + (k >> 4)];
            int n = NT - k;
            float2 zn = buf[n + (n >> 4)];
            float ra = zk.x + zn.x, ia = zk.y - zn.y;
            float rb = zk.y + zn.y, ib = zn.x - zk.x;
            ampA[k] = ra * ra + ia * ia;
            ampB[k] = rb * rb + ib * ib;
        }
    }
    __syncthreads();

    int lane = tid & 31, wid = tid >> 5;
    if (wid < 4)
        topk_group(ampA, buf, wmax,     tid,       wid,     lane, series0,     false, 1);
    else
        topk_group(ampB, buf, wmax + 8, tid - 128, wid - 4, lane, series0 + 1, true,  2);
}

// ---------------------------------------------------------------------------
// Kernel 3: reconstruction via Chebyshev recurrence
// ---------------------------------------------------------------------------
__global__ __launch_bounds__(256) void recon_kernel(float* __restrict__ out) {
    int d  = blockIdx.x * 256 + threadIdx.x;   // gridDim.x = 2
    int b  = blockIdx.z;
    int t0 = blockIdx.y * TCHUNK;
    int series = b * ND + d;

    float ycur[TOPK], yprev[TOPK], twocw[TOPK];
#pragma unroll
    for (int j = 0; j < TOPK; j++) {
        float4 cf = __ldg(&g_coef[series * TOPK + j]);
        int k = (int)cf.x;
        float c2 = cf.y, s2 = cf.z;
        int m0 = (k * t0) & 4095;          // exact angle reduction mod 2*pi
        int m1 = (m0 - k) & 4095;          // angle at t0-1
        float ss, cc;
        sincospif((float)m0 * (1.0f / 2048.0f), &ss, &cc);
        ycur[j]  = c2 * cc - s2 * ss;
        sincospif((float)m1 * (1.0f / 2048.0f), &ss, &cc);
        yprev[j] = c2 * cc - s2 * ss;
        sincospif((float)k * (1.0f / 2048.0f), &ss, &cc);
        twocw[j] = 2.0f * cc;
    }
    float* op = out + ((size_t)b * NT + t0) * ND + d;
#pragma unroll 4
    for (int tt = 0; tt < TCHUNK; tt++) {
        float acc = 0.0f;
#pragma unroll
        for (int j = 0; j < TOPK; j++)
            acc += ycur[j];
        op[(size_t)tt * ND] = acc;
#pragma unroll
        for (int j = 0; j < TOPK; j++) {
            float yn = twocw[j] * ycur[j] - yprev[j];
            yprev[j] = ycur[j];
            ycur[j]  = yn;
        }
    }
}

// ---------------------------------------------------------------------------
extern "C" void kernel_launch(void* const* d_in, const int* in_sizes, int n_in,
                              void* d_out, int out_size) {
    const float* x = (const float*)d_in[0];
    float* out = (float*)d_out;

    dim3 g1(16, 16, NB);   // i-blocks, pair-blocks, batch
    fft16a_kernel<<<g1, 256>>>(x);

    size_t shmem = 4352 * sizeof(float2) + 4096 * sizeof(float);  // 51200 B
    cudaFuncSetAttribute(fft_topk_kernel,
                         cudaFuncAttributeMaxDynamicSharedMemorySize, (int)shmem);
    fft_topk_kernel<<<NPAIR, 256, shmem>>>();

    dim3 rg(ND / 256, NT / TCHUNK, NB);
    recon_kernel<<<rg, 256>>>(out);
}